// round 16
// baseline (speedup 1.0000x reference)
#include <cuda_runtime.h>
#include <cuda_bf16.h>
#include <math.h>
#include <stdint.h>

#define BATCH 2
#define SEQ   2048
#define DIM   2048
#define NHEAD 8
#define HDIM  256
#define EDIM  (NHEAD * HDIM)   // 2048
#define MROWS (BATCH * SEQ)    // 4096
#define NCB   (SEQ / 128)      // 16 col-blocks per row

// ---------------- scratch (device globals; no cudaMalloc allowed) ----------
__device__ float g_QKVf[(size_t)3 * MROWS * EDIM];          // Q|K|V fp32
__device__ float g_sin[SEQ * (HDIM / 2)];
__device__ float g_cos[SEQ * (HDIM / 2)];
__device__ float g_rowm[(size_t)BATCH * NHEAD * NCB * SEQ]; // per-block row max
__device__ float g_rowl[(size_t)BATCH * NHEAD * NCB * SEQ]; // per-block row sumexp

// bf16 hi/lo operand pairs
__device__ __nv_bfloat16 g_Eh [(size_t)BATCH * NHEAD * SEQ * SEQ];  // E hi
__device__ __nv_bfloat16 g_El [(size_t)BATCH * NHEAD * SEQ * SEQ];  // E lo
__device__ __nv_bfloat16 g_xh [(size_t)MROWS * DIM],  g_xl [(size_t)MROWS * DIM];
__device__ __nv_bfloat16 g_Wh [(size_t)3 * EDIM * DIM], g_Wl [(size_t)3 * EDIM * DIM];
__device__ __nv_bfloat16 g_Woh[(size_t)DIM * EDIM],   g_Wol[(size_t)DIM * EDIM];
__device__ __nv_bfloat16 g_Qh [(size_t)MROWS * EDIM], g_Ql [(size_t)MROWS * EDIM];
__device__ __nv_bfloat16 g_Kh [(size_t)MROWS * EDIM], g_Kl [(size_t)MROWS * EDIM];
__device__ __nv_bfloat16 g_Vth[(size_t)MROWS * EDIM], g_Vtl[(size_t)MROWS * EDIM];
__device__ __nv_bfloat16 g_Oh [(size_t)MROWS * EDIM], g_Ol [(size_t)MROWS * EDIM];

// ---------------- helpers ----------------------------------------------------
__device__ __forceinline__ uint32_t s2u(const void* p) {
    return (uint32_t)__cvta_generic_to_shared(p);
}
__device__ __forceinline__ void cpa16(uint32_t s, const void* g) {
    asm volatile("cp.async.cg.shared.global [%0], [%1], 16;" :: "r"(s), "l"(g));
}
#define CP_COMMIT() asm volatile("cp.async.commit_group;" ::: "memory")
#define CP_WAIT1()  asm volatile("cp.async.wait_group 1;" ::: "memory")

// split two floats -> hi bf16x2 + residual lo bf16x2 (x in low 16 bits)
__device__ __forceinline__ void pack_split(float2 f, uint32_t& hi, uint32_t& lo) {
    uint32_t h;
    asm("cvt.rn.bf16x2.f32 %0, %1, %2;" : "=r"(h) : "f"(f.y), "f"(f.x));
    float fyh = __uint_as_float(h & 0xffff0000u);
    float fxh = __uint_as_float(h << 16);
    asm("cvt.rn.bf16x2.f32 %0, %1, %2;" : "=r"(lo) : "f"(f.y - fyh), "f"(f.x - fxh));
    hi = h;
}

__device__ __forceinline__ void mma16816(float* c, const uint32_t* a, const uint32_t* b) {
    asm volatile("mma.sync.aligned.m16n8k16.row.col.f32.bf16.bf16.f32 "
        "{%0,%1,%2,%3},{%4,%5,%6,%7},{%8,%9},{%0,%1,%2,%3};"
        : "+f"(c[0]), "+f"(c[1]), "+f"(c[2]), "+f"(c[3])
        : "r"(a[0]), "r"(a[1]), "r"(a[2]), "r"(a[3]), "r"(b[0]), "r"(b[1]));
}

#define LDSM4(R, addr)                                                          \
    asm volatile("ldmatrix.sync.aligned.m8n8.x4.shared.b16 {%0,%1,%2,%3}, [%4];"\
        : "=r"((R)[0]), "=r"((R)[1]), "=r"((R)[2]), "=r"((R)[3]) : "r"(addr))

// swizzle inside a 128x16 bf16 subtile stored as 16B chunks (row, half-of-k16)
__device__ __forceinline__ uint32_t chunkoff(int row, int half) {
    const int line = row >> 2;
    const int cp = ((row & 3) << 1) | half;
    return (uint32_t)(line * 128 + ((cp ^ (line & 7)) << 4));
}

// ---------------- bf16x3-split tensor-core GEMM (R5-proven mainloop) ---------
// C[m][n] = alpha * sum_k (Ah+Al)[m][k] * (Bh+Bl)[n][k]  (lo*lo dropped)
// STATS: causal scores; epilogue emits per-(row,128-col-block) (max,sumexp)
//        and stores E = exp(s - rowblockmax) packed as bf16 hi/lo (Chg/Clg).
#define BM 128
#define BN 128
#define BK 32
#define NS 3
#define T_AHI 0
#define T_ALO 8192
#define T_BHI 16384
#define T_BLO 24576
#define STG   32768
#define GEMM_SMEM (NS * STG)     // 98304

template<bool CAUSAL, bool STATS>
__global__ void __launch_bounds__(256, 2)
gemm_bf3(const __nv_bfloat16* __restrict__ Ahg, const __nv_bfloat16* __restrict__ Alg,
         const __nv_bfloat16* __restrict__ Bhg, const __nv_bfloat16* __restrict__ Blg,
         float* __restrict__ Cg, __nv_bfloat16* __restrict__ Chg, __nv_bfloat16* __restrict__ Clg,
         int K, int lda, int ldb, int ldc, int batch_inner,
         long sa_out, long sa_in, long sb_out, long sb_in,
         long sc_out, long sc_in, float alpha)
{
    const int m0 = blockIdx.y * BM;
    const int n0 = blockIdx.x * BN;
    if (CAUSAL && n0 > m0 + BM - 1) return;

    const int z = blockIdx.z, zo = z / batch_inner, zi = z % batch_inner;
    const __nv_bfloat16* Ah = Ahg + zo * sa_out + zi * sa_in + (long)m0 * lda;
    const __nv_bfloat16* Al = Alg + zo * sa_out + zi * sa_in + (long)m0 * lda;
    const __nv_bfloat16* Bh = Bhg + zo * sb_out + zi * sb_in + (long)n0 * ldb;
    const __nv_bfloat16* Bl = Blg + zo * sb_out + zi * sb_in + (long)n0 * ldb;

    extern __shared__ __align__(128) char smem[];
    const uint32_t sbase = s2u(smem);

    const int tid = threadIdx.x, wid = tid >> 5, lane = tid & 31;
    const int wm = wid >> 2, wn = wid & 3;           // warp grid 2 x 4
    const int warp_row = wm * 64, warp_col = wn * 32;

    const int nk = K / BK;

    // ldmatrix geometry (sub-tile 0 offsets; sub 1 adds 4096)
    const int mat = lane >> 3;
    const int lrow = ((mat & 1) << 3) | (lane & 7);
    const int lhalf = mat >> 1;
    uint32_t aoff[4];
#pragma unroll
    for (int i = 0; i < 4; i++)
        aoff[i] = chunkoff(warp_row + i * 16 + lrow, lhalf);
    const int bj = mat >> 1, bhh = mat & 1;
    const uint32_t boff0 = chunkoff(warp_col + bj * 8 + (lane & 7), bhh);
    const uint32_t boff1 = chunkoff(warp_col + 16 + bj * 8 + (lane & 7), bhh);

    auto load_stage = [&](int stage) {
        if (stage >= nk) return;
        const uint32_t s0 = sbase + (stage % NS) * STG;
        const long k0 = (long)stage * BK;
#pragma unroll
        for (int j = 0; j < 2; j++) {
            const int c = tid + j * 256;
            const int row = c >> 2, sub = (c >> 1) & 1, half = c & 1;
            const uint32_t doff = sub * 4096 + chunkoff(row, half);
            const long goff = k0 + sub * 16 + half * 8;
            cpa16(s0 + T_AHI + doff, Ah + (long)row * lda + goff);
            cpa16(s0 + T_ALO + doff, Al + (long)row * lda + goff);
            cpa16(s0 + T_BHI + doff, Bh + (long)row * ldb + goff);
            cpa16(s0 + T_BLO + doff, Bl + (long)row * ldb + goff);
        }
    };

    float acc[4][4][4];
#pragma unroll
    for (int i = 0; i < 4; i++)
#pragma unroll
        for (int j = 0; j < 4; j++)
#pragma unroll
            for (int e = 0; e < 4; e++) acc[i][j][e] = 0.f;

    load_stage(0); CP_COMMIT();
    load_stage(1); CP_COMMIT();

    for (int it = 0; it < nk; it++) {
        CP_WAIT1();
        __syncthreads();
        const uint32_t s0 = sbase + (it % NS) * STG;
#pragma unroll
        for (int sub = 0; sub < 2; sub++) {
            const uint32_t so = s0 + sub * 4096;
            uint32_t bhr[8], blr[8];
            LDSM4(bhr + 0, so + T_BHI + boff0);
            LDSM4(bhr + 4, so + T_BHI + boff1);
            LDSM4(blr + 0, so + T_BLO + boff0);
            LDSM4(blr + 4, so + T_BLO + boff1);
#pragma unroll
            for (int i = 0; i < 4; i++) {
                uint32_t ah[4], al[4];
                LDSM4(ah, so + T_AHI + aoff[i]);
                LDSM4(al, so + T_ALO + aoff[i]);
#pragma unroll
                for (int j = 0; j < 4; j++) {
                    mma16816(acc[i][j], ah, &bhr[j * 2]);   // hi*hi
                    mma16816(acc[i][j], ah, &blr[j * 2]);   // hi*lo
                    mma16816(acc[i][j], al, &bhr[j * 2]);   // lo*hi
                }
            }
        }
        load_stage(it + 2);
        CP_COMMIT();
    }

    // ---------------- epilogue ----------------
    const int r  = lane >> 2;
    const int cq = (lane & 3) * 2;

#pragma unroll
    for (int i = 0; i < 4; i++)
#pragma unroll
        for (int j = 0; j < 4; j++) {
            const int col = n0 + warp_col + j * 8 + cq;
            const int row0 = m0 + warp_row + i * 16 + r;
            const int row1 = row0 + 8;
            acc[i][j][0] *= alpha; acc[i][j][1] *= alpha;
            acc[i][j][2] *= alpha; acc[i][j][3] *= alpha;
            if (CAUSAL) {
                if (col     > row0) acc[i][j][0] = -1e30f;
                if (col + 1 > row0) acc[i][j][1] = -1e30f;
                if (col     > row1) acc[i][j][2] = -1e30f;
                if (col + 1 > row1) acc[i][j][3] = -1e30f;
            }
        }

    if (STATS) {
        __syncthreads();                    // stage smem now dead -> reuse
        float* redm = (float*)smem;         // [4][128]
        float* redl = redm + 512;           // [4][128]
        float* smM  = redm + 1024;          // [128]

        float lm[2][4];
#pragma unroll
        for (int i = 0; i < 4; i++) {
            float a0 = -1e30f, a1 = -1e30f;
#pragma unroll
            for (int j = 0; j < 4; j++) {
                a0 = fmaxf(a0, fmaxf(acc[i][j][0], acc[i][j][1]));
                a1 = fmaxf(a1, fmaxf(acc[i][j][2], acc[i][j][3]));
            }
            lm[0][i] = a0; lm[1][i] = a1;
        }
#pragma unroll
        for (int o = 1; o <= 2; o <<= 1)
#pragma unroll
            for (int i = 0; i < 4; i++) {
                lm[0][i] = fmaxf(lm[0][i], __shfl_xor_sync(0xffffffffu, lm[0][i], o));
                lm[1][i] = fmaxf(lm[1][i], __shfl_xor_sync(0xffffffffu, lm[1][i], o));
            }
        if ((lane & 3) == 0) {
#pragma unroll
            for (int i = 0; i < 4; i++) {
                redm[wn * 128 + warp_row + i * 16 + r]     = lm[0][i];
                redm[wn * 128 + warp_row + i * 16 + r + 8] = lm[1][i];
            }
        }
        __syncthreads();
        if (tid < 128)
            smM[tid] = fmaxf(fmaxf(redm[tid], redm[128 + tid]),
                             fmaxf(redm[256 + tid], redm[384 + tid]));
        __syncthreads();

        // exp pass: overwrite acc with E = exp(acc - M); accumulate sums
        float ls[2][4];
#pragma unroll
        for (int i = 0; i < 4; i++) {
            const float M0 = smM[warp_row + i * 16 + r];
            const float M1 = smM[warp_row + i * 16 + r + 8];
            float s0 = 0.f, s1 = 0.f;
#pragma unroll
            for (int j = 0; j < 4; j++) {
                const float e0 = __expf(acc[i][j][0] - M0);
                const float e1 = __expf(acc[i][j][1] - M0);
                const float e2 = __expf(acc[i][j][2] - M1);
                const float e3 = __expf(acc[i][j][3] - M1);
                acc[i][j][0] = e0; acc[i][j][1] = e1;
                acc[i][j][2] = e2; acc[i][j][3] = e3;
                s0 += e0 + e1;
                s1 += e2 + e3;
            }
            ls[0][i] = s0; ls[1][i] = s1;
        }
#pragma unroll
        for (int o = 1; o <= 2; o <<= 1)
#pragma unroll
            for (int i = 0; i < 4; i++) {
                ls[0][i] += __shfl_xor_sync(0xffffffffu, ls[0][i], o);
                ls[1][i] += __shfl_xor_sync(0xffffffffu, ls[1][i], o);
            }
        if ((lane & 3) == 0) {
#pragma unroll
            for (int i = 0; i < 4; i++) {
                redl[wn * 128 + warp_row + i * 16 + r]     = ls[0][i];
                redl[wn * 128 + warp_row + i * 16 + r + 8] = ls[1][i];
            }
        }
        __syncthreads();
        if (tid < 128) {
            const float L = redl[tid] + redl[128 + tid]
                          + redl[256 + tid] + redl[384 + tid];
            const long si = ((long)z * NCB + (n0 >> 7)) * SEQ + m0 + tid;
            g_rowm[si] = smM[tid];
            g_rowl[si] = L;
        }

        // store E packed bf16 hi/lo
        __nv_bfloat16* Eh = Chg + zo * sc_out + zi * sc_in;
        __nv_bfloat16* El = Clg + zo * sc_out + zi * sc_in;
#pragma unroll
        for (int i = 0; i < 4; i++) {
#pragma unroll
            for (int j = 0; j < 4; j++) {
                const int col = n0 + warp_col + j * 8 + cq;
                const int row0 = m0 + warp_row + i * 16 + r;
                const int row1 = row0 + 8;
                uint32_t h0, l0, h1, l1;
                pack_split(make_float2(acc[i][j][0], acc[i][j][1]), h0, l0);
                pack_split(make_float2(acc[i][j][2], acc[i][j][3]), h1, l1);
                *(uint32_t*)(Eh + (long)row0 * ldc + col) = h0;
                *(uint32_t*)(El + (long)row0 * ldc + col) = l0;
                *(uint32_t*)(Eh + (long)row1 * ldc + col) = h1;
                *(uint32_t*)(El + (long)row1 * ldc + col) = l1;
            }
        }
        return;
    }

    // store C fp32
    float* C = Cg + zo * sc_out + zi * sc_in;
#pragma unroll
    for (int i = 0; i < 4; i++) {
#pragma unroll
        for (int j = 0; j < 4; j++) {
            const int col = n0 + warp_col + j * 8 + cq;
            const int row0 = m0 + warp_row + i * 16 + r;
            const int row1 = row0 + 8;
            *(float2*)(C + (long)row0 * ldc + col) =
                make_float2(acc[i][j][0], acc[i][j][1]);
            *(float2*)(C + (long)row1 * ldc + col) =
                make_float2(acc[i][j][2], acc[i][j][3]);
        }
    }
}

// ---------------- fused PV v4: P = E(bf16 hi/lo) with acc rescale ------------
// O[m0..+128)[n0..+128) = sum_cb f[row][cb] * (E_cb @ V_cb)
// Mainloop structurally identical to gemm_bf3 (pure cp.async + LDSM + MMA);
// the softmax scale is applied as a flash-style accumulator rescale at each
// 128-col-block boundary plus a final scale.
#define FPS_SCALE (NS * STG)               // sm_f at 98304
#define FP_SMEM   (NS * STG + NCB * 128 * 4)  // 106496

__global__ void __launch_bounds__(256, 2)
flashpv(const __nv_bfloat16* __restrict__ Ehg, const __nv_bfloat16* __restrict__ Elg,
        const __nv_bfloat16* __restrict__ Vth, const __nv_bfloat16* __restrict__ Vtl,
        __nv_bfloat16* __restrict__ Oh, __nv_bfloat16* __restrict__ Ol)
{
    const int n0 = blockIdx.x * 128;          // d cols
    const int m0 = blockIdx.y * 128;          // q rows
    const int bh = blockIdx.z;
    const int b = bh / NHEAD, h = bh % NHEAD;

    const __nv_bfloat16* Ah = Ehg + (long)bh * SEQ * SEQ + (long)m0 * SEQ;
    const __nv_bfloat16* Al = Elg + (long)bh * SEQ * SEQ + (long)m0 * SEQ;
    const __nv_bfloat16* Bh = Vth + ((long)bh * HDIM + n0) * SEQ;
    const __nv_bfloat16* Bl = Vtl + ((long)bh * HDIM + n0) * SEQ;

    extern __shared__ __align__(128) char smem[];
    const uint32_t sbase = s2u(smem);
    float* sm_f = (float*)(smem + FPS_SCALE);   // [NCB][128]

    const int tid = threadIdx.x, wid = tid >> 5, lane = tid & 31;
    const int wm = wid >> 2, wn = wid & 3;
    const int warp_row = wm * 64, warp_col = wn * 32;
    const int r  = lane >> 2;
    const int cq = (lane & 3) * 2;
    const int nk = (m0 + 128) / 32;            // multiple of 4

    // combine per-block stats -> per-(row, col-block) scale f = exp(m_cb-M)/L
    if (tid < 128) {
        const int nb = (m0 >> 7) + 1;
        float M = -1e30f, L = 0.f;
        for (int cb = 0; cb < nb; cb++) {
            const long si = ((long)bh * NCB + cb) * SEQ + m0 + tid;
            const float m = g_rowm[si];
            const float l = g_rowl[si];
            const float nm = fmaxf(M, m);
            L = L * __expf(M - nm) + l * __expf(m - nm);
            M = nm;
        }
        const float invL = 1.0f / L;
        for (int cb = 0; cb < nb; cb++) {
            const long si = ((long)bh * NCB + cb) * SEQ + m0 + tid;
            sm_f[cb * 128 + tid] = __expf(g_rowm[si] - M) * invL;
        }
    }

    // ldmatrix geometry (identical to gemm_bf3)
    const int mat = lane >> 3;
    const int lrow = ((mat & 1) << 3) | (lane & 7);
    const int lhalf = mat >> 1;
    uint32_t aoff[4];
#pragma unroll
    for (int i = 0; i < 4; i++)
        aoff[i] = chunkoff(warp_row + i * 16 + lrow, lhalf);
    const int bj = mat >> 1, bhh = mat & 1;
    const uint32_t boff0 = chunkoff(warp_col + bj * 8 + (lane & 7), bhh);
    const uint32_t boff1 = chunkoff(warp_col + 16 + bj * 8 + (lane & 7), bhh);

    auto load_stage = [&](int stage) {
        if (stage >= nk) return;
        const uint32_t s0 = sbase + (stage % NS) * STG;
        const long k0 = (long)stage * BK;
#pragma unroll
        for (int j = 0; j < 2; j++) {
            const int c = tid + j * 256;
            const int row = c >> 2, sub = (c >> 1) & 1, half = c & 1;
            const uint32_t doff = sub * 4096 + chunkoff(row, half);
            const long goff = k0 + sub * 16 + half * 8;
            cpa16(s0 + T_AHI + doff, Ah + (long)row * SEQ + goff);
            cpa16(s0 + T_ALO + doff, Al + (long)row * SEQ + goff);
            cpa16(s0 + T_BHI + doff, Bh + (long)row * SEQ + goff);
            cpa16(s0 + T_BLO + doff, Bl + (long)row * SEQ + goff);
        }
    };

    float acc[4][4][4];
#pragma unroll
    for (int i = 0; i < 4; i++)
#pragma unroll
        for (int j = 0; j < 4; j++)
#pragma unroll
            for (int e = 0; e < 4; e++) acc[i][j][e] = 0.f;

    float fc0[4], fc1[4];

    load_stage(0); CP_COMMIT();
    load_stage(1); CP_COMMIT();
    __syncthreads();                       // sm_f visible to all

    for (int it = 0; it < nk; it++) {
        CP_WAIT1();
        __syncthreads();

        if ((it & 3) == 0) {               // 128-col-block boundary: rescale
            const int cb = it >> 2;
#pragma unroll
            for (int i = 0; i < 4; i++) {
                const float nf0 = sm_f[cb * 128 + warp_row + i * 16 + r];
                const float nf1 = sm_f[cb * 128 + warp_row + i * 16 + r + 8];
                if (it) {
                    const float r0 = __fdividef(fc0[i], nf0);
                    const float r1 = __fdividef(fc1[i], nf1);
#pragma unroll
                    for (int j = 0; j < 4; j++) {
                        acc[i][j][0] *= r0; acc[i][j][1] *= r0;
                        acc[i][j][2] *= r1; acc[i][j][3] *= r1;
                    }
                }
                fc0[i] = nf0; fc1[i] = nf1;
            }
        }

        const uint32_t s0 = sbase + (it % NS) * STG;
#pragma unroll
        for (int sub = 0; sub < 2; sub++) {
            const uint32_t so = s0 + sub * 4096;
            uint32_t bhr[8], blr[8];
            LDSM4(bhr + 0, so + T_BHI + boff0);
            LDSM4(bhr + 4, so + T_BHI + boff1);
            LDSM4(blr + 0, so + T_BLO + boff0);
            LDSM4(blr + 4, so + T_BLO + boff1);
#pragma unroll
            for (int i = 0; i < 4; i++) {
                uint32_t ah[4], al[4];
                LDSM4(ah, so + T_AHI + aoff[i]);
                LDSM4(al, so + T_ALO + aoff[i]);
#pragma unroll
                for (int j = 0; j < 4; j++) {
                    mma16816(acc[i][j], ah, &bhr[j * 2]);   // Eh*Vh
                    mma16816(acc[i][j], ah, &blr[j * 2]);   // Eh*Vl
                    mma16816(acc[i][j], al, &bhr[j * 2]);   // El*Vh
                }
            }
        }
        load_stage(it + 2);
        CP_COMMIT();
    }

    // epilogue: final scale by f_last, write O bf16 hi/lo
    __nv_bfloat16* Ch = Oh + (long)b * SEQ * EDIM + h * HDIM;
    __nv_bfloat16* Cl = Ol + (long)b * SEQ * EDIM + h * HDIM;
#pragma unroll
    for (int i = 0; i < 4; i++) {
#pragma unroll
        for (int j = 0; j < 4; j++) {
            const int col = n0 + warp_col + j * 8 + cq;
            const int row0 = m0 + warp_row + i * 16 + r;
            const int row1 = row0 + 8;
            uint32_t h0, l0, h1, l1;
            pack_split(make_float2(acc[i][j][0] * fc0[i], acc[i][j][1] * fc0[i]), h0, l0);
            pack_split(make_float2(acc[i][j][2] * fc1[i], acc[i][j][3] * fc1[i]), h1, l1);
            *(uint32_t*)(Ch + (long)row0 * EDIM + col) = h0;
            *(uint32_t*)(Cl + (long)row0 * EDIM + col) = l0;
            *(uint32_t*)(Ch + (long)row1 * EDIM + col) = h1;
            *(uint32_t*)(Cl + (long)row1 * EDIM + col) = l1;
        }
    }
}

// ---------------- single-launch fp32 -> bf16 hi/lo split for ALL inputs ------
#define SPLIT_BLKS_X  8192
#define SPLIT_BLKS_W  4096
#define SPLIT_TOTAL_BLKS (SPLIT_BLKS_X + 4 * SPLIT_BLKS_W)

__global__ void __launch_bounds__(256)
split_all(const float* __restrict__ x,  const float* __restrict__ Wq,
          const float* __restrict__ Wk, const float* __restrict__ Wv,
          const float* __restrict__ Wo,
          __nv_bfloat16* __restrict__ xh,  __nv_bfloat16* __restrict__ xl,
          __nv_bfloat16* __restrict__ Wh,  __nv_bfloat16* __restrict__ Wl,
          __nv_bfloat16* __restrict__ Woh, __nv_bfloat16* __restrict__ Wol)
{
    const long WS = (long)EDIM * DIM;
    const int blk = blockIdx.x;
    const float* src;
    __nv_bfloat16 *hi, *lo;
    long i;
    if (blk < SPLIT_BLKS_X) {
        src = x; hi = xh; lo = xl;
        i = (long)blk * 256 + threadIdx.x;
    } else if (blk < SPLIT_BLKS_X + SPLIT_BLKS_W) {
        src = Wq; hi = Wh; lo = Wl;
        i = (long)(blk - SPLIT_BLKS_X) * 256 + threadIdx.x;
    } else if (blk < SPLIT_BLKS_X + 2 * SPLIT_BLKS_W) {
        src = Wk; hi = Wh + WS; lo = Wl + WS;
        i = (long)(blk - SPLIT_BLKS_X - SPLIT_BLKS_W) * 256 + threadIdx.x;
    } else if (blk < SPLIT_BLKS_X + 3 * SPLIT_BLKS_W) {
        src = Wv; hi = Wh + 2 * WS; lo = Wl + 2 * WS;
        i = (long)(blk - SPLIT_BLKS_X - 2 * SPLIT_BLKS_W) * 256 + threadIdx.x;
    } else {
        src = Wo; hi = Woh; lo = Wol;
        i = (long)(blk - SPLIT_BLKS_X - 3 * SPLIT_BLKS_W) * 256 + threadIdx.x;
    }
    const float4 v = ((const float4*)src)[i];
    uint32_t h0, l0, h1, l1;
    pack_split(make_float2(v.x, v.y), h0, l0);
    pack_split(make_float2(v.z, v.w), h1, l1);
    ((uint2*)hi)[i] = make_uint2(h0, h1);
    ((uint2*)lo)[i] = make_uint2(l0, l1);
}

// ---------------- warp reductions ------------------------------------------
__device__ __forceinline__ float warp_sum(float v) {
#pragma unroll
    for (int o = 16; o; o >>= 1) v += __shfl_xor_sync(0xffffffffu, v, o);
    return v;
}

// ---------------- RoPE tables (fp64, once) ----------------------------------
__global__ void __launch_bounds__(256)
rope_tables(const int* __restrict__ pos) {
    const int i = blockIdx.x * 256 + threadIdx.x;
    const int s = i >> 7, fi = i & 127;
    const double inv = exp(-(double)fi * (9.210340371976184 / 128.0));
    const double ang = (double)pos[s] * inv;
    g_sin[i] = (float)sin(ang);
    g_cos[i] = (float)cos(ang);
}

// ---------------- fused RMSNorm + RoPE (Q and K in one launch) ---------------
__global__ void __launch_bounds__(HDIM)
rmsnorm_rope_split(const float* __restrict__ Qf, const float* __restrict__ Kf,
                   const float* __restrict__ qw, const float* __restrict__ kw,
                   __nv_bfloat16* __restrict__ Qh, __nv_bfloat16* __restrict__ Ql,
                   __nv_bfloat16* __restrict__ Kh, __nv_bfloat16* __restrict__ Kl)
{
    const int h = blockIdx.x, s = blockIdx.y, t = threadIdx.x;
    const int b = blockIdx.z & 1, sel = blockIdx.z >> 1;
    const float* X = sel ? Kf : Qf;
    const float* w = sel ? kw : qw;
    __nv_bfloat16* Xh = sel ? Kh : Qh;
    __nv_bfloat16* Xl = sel ? Kl : Ql;

    __shared__ float buf[HDIM];
    __shared__ float red[8];

    const int half = HDIM / 2;
    const int fi = (t < half) ? t : t - half;
    const float cs = g_cos[s * half + fi];
    const float sn = g_sin[s * half + fi];

    const long idx = ((long)(b * SEQ + s)) * EDIM + h * HDIM + t;
    const float x = X[idx];
    const int wid = t >> 5, lane = t & 31;

    float ss = warp_sum(x * x);
    if (lane == 0) red[wid] = ss;
    __syncthreads();
    float tot = 0.f;
#pragma unroll
    for (int rr = 0; rr < 8; rr++) tot += red[rr];

    const float xn = x * rsqrtf(tot * (1.0f / HDIM) + 1e-6f) * w[t];
    buf[t] = xn;
    __syncthreads();

    float out;
    if (t < half) out = xn * cs - buf[t + half] * sn;
    else          out = xn * cs + buf[t - half] * sn;

    const __nv_bfloat16 oh = __float2bfloat16(out);
    Xh[idx] = oh;
    Xl[idx] = __float2bfloat16(out - __bfloat162float(oh));
}

// ---------------- V transpose -> bf16 hi/lo  Vt[bh][d][s] --------------------
__global__ void __launch_bounds__(256)
transpose_v_split(const float* __restrict__ V,
                  __nv_bfloat16* __restrict__ Vth, __nv_bfloat16* __restrict__ Vtl)
{
    __shared__ float tile[32][33];
    const int bh = blockIdx.z;
    const int b = bh / NHEAD, h = bh % NHEAD;
    const int s0 = blockIdx.x * 32, d0 = blockIdx.y * 32;
    const int tx = threadIdx.x & 31, ty = threadIdx.x >> 5;

    const float* src = V + (long)b * SEQ * EDIM + h * HDIM;
#pragma unroll
    for (int i = ty; i < 32; i += 8)
        tile[i][tx] = src[(long)(s0 + i) * EDIM + d0 + tx];
    __syncthreads();
    const long dbase = ((long)bh * HDIM + d0) * SEQ + s0;
#pragma unroll
    for (int i = ty; i < 32; i += 8) {
        const float v = tile[tx][i];
        const __nv_bfloat16 vh = __float2bfloat16(v);
        Vth[dbase + (long)i * SEQ + tx] = vh;
        Vtl[dbase + (long)i * SEQ + tx] = __float2bfloat16(v - __bfloat162float(vh));
    }
}

// ---------------- launcher ---------------------------------------------------
extern "C" void kernel_launch(void* const* d_in, const int* in_sizes, int n_in,
                              void* d_out, int out_size)
{
    const float* x   = (const float*)d_in[0];
    const int*   pos = (const int*)  d_in[1];
    const float* Wq  = (const float*)d_in[2];
    const float* Wk  = (const float*)d_in[3];
    const float* Wv  = (const float*)d_in[4];
    const float* Wo  = (const float*)d_in[5];
    const float* qw  = (const float*)d_in[6];
    const float* kw  = (const float*)d_in[7];
    float* out = (float*)d_out;

    float* QKVf;
    cudaGetSymbolAddress((void**)&QKVf, g_QKVf);
    float* Q = QKVf;
    float* K = QKVf + (size_t)MROWS * EDIM;
    float* V = QKVf + (size_t)2 * MROWS * EDIM;

    __nv_bfloat16 *Eh, *El, *xh, *xl, *Wh, *Wl, *Woh, *Wol;
    __nv_bfloat16 *Qh, *Ql, *Kh, *Kl, *Vth, *Vtl, *Oh, *Ol;
    cudaGetSymbolAddress((void**)&Eh,  g_Eh);  cudaGetSymbolAddress((void**)&El,  g_El);
    cudaGetSymbolAddress((void**)&xh,  g_xh);  cudaGetSymbolAddress((void**)&xl,  g_xl);
    cudaGetSymbolAddress((void**)&Wh,  g_Wh);  cudaGetSymbolAddress((void**)&Wl,  g_Wl);
    cudaGetSymbolAddress((void**)&Woh, g_Woh); cudaGetSymbolAddress((void**)&Wol, g_Wol);
    cudaGetSymbolAddress((void**)&Qh,  g_Qh);  cudaGetSymbolAddress((void**)&Ql,  g_Ql);
    cudaGetSymbolAddress((void**)&Kh,  g_Kh);  cudaGetSymbolAddress((void**)&Kl,  g_Kl);
    cudaGetSymbolAddress((void**)&Vth, g_Vth); cudaGetSymbolAddress((void**)&Vtl, g_Vtl);
    cudaGetSymbolAddress((void**)&Oh,  g_Oh);  cudaGetSymbolAddress((void**)&Ol,  g_Ol);

    cudaFuncSetAttribute(gemm_bf3<false, false>,
        cudaFuncAttributeMaxDynamicSharedMemorySize, GEMM_SMEM);
    cudaFuncSetAttribute(gemm_bf3<true, true>,
        cudaFuncAttributeMaxDynamicSharedMemorySize, GEMM_SMEM);
    cudaFuncSetAttribute(flashpv,
        cudaFuncAttributeMaxDynamicSharedMemorySize, FP_SMEM);

    const dim3 blk(256);
    const long SS = (long)SEQ * SEQ;
    const long WSTRIDE = (long)EDIM * DIM;

    rope_tables<<<(SEQ * (HDIM / 2)) / 256, 256>>>(pos);

    // 0) all fp32 -> bf16 hi/lo splits in ONE launch
    split_all<<<SPLIT_TOTAL_BLKS, 256>>>(x, Wq, Wk, Wv, Wo,
                                         xh, xl, Wh, Wl, Woh, Wol);

    // 1) QKV projections (3 launches; per-launch working set fits L2)
    const dim3 g1(EDIM / BN, MROWS / BM, 1);
    gemm_bf3<false, false><<<g1, blk, GEMM_SMEM>>>(xh, xl, Wh, Wl,
        Q, nullptr, nullptr, DIM, DIM, DIM, EDIM, 1, 0, 0, 0, 0, 0, 0, 1.0f);
    gemm_bf3<false, false><<<g1, blk, GEMM_SMEM>>>(xh, xl, Wh + WSTRIDE, Wl + WSTRIDE,
        K, nullptr, nullptr, DIM, DIM, DIM, EDIM, 1, 0, 0, 0, 0, 0, 0, 1.0f);
    gemm_bf3<false, false><<<g1, blk, GEMM_SMEM>>>(xh, xl, Wh + 2 * WSTRIDE, Wl + 2 * WSTRIDE,
        V, nullptr, nullptr, DIM, DIM, DIM, EDIM, 1, 0, 0, 0, 0, 0, 0, 1.0f);

    // 2) RMSNorm + RoPE on Q and K (one launch, z selects)
    rmsnorm_rope_split<<<dim3(NHEAD, SEQ, BATCH * 2), HDIM>>>(
        Q, K, qw, kw, Qh, Ql, Kh, Kl);

    // 2b) transpose V -> bf16 hi/lo  [bh][d][s]
    transpose_v_split<<<dim3(SEQ / 32, HDIM / 32, BATCH * NHEAD), 256>>>(V, Vth, Vtl);

    // 3) E = exp(scores - rowblockmax) packed bf16 hi/lo, with per-block stats
    const dim3 g2(SEQ / BN, SEQ / BM, BATCH * NHEAD);
    gemm_bf3<true, true><<<g2, blk, GEMM_SMEM>>>(Qh, Ql, Kh, Kl,
        nullptr, Eh, El, HDIM, EDIM, EDIM, SEQ,
        NHEAD, (long)SEQ * EDIM, HDIM, (long)SEQ * EDIM, HDIM,
        (long)NHEAD * SS, SS, 0.0625f);

    // 4+5) fused PV with accumulator rescale -> O bf16 hi/lo
    flashpv<<<dim3(HDIM / 128, SEQ / 128, BATCH * NHEAD), blk, FP_SMEM>>>(
        Eh, El, Vth, Vtl, Oh, Ol);

    // 6) out = O Wo^T (fp32 out)
    const dim3 g4(DIM / BN, MROWS / BM, 1);
    gemm_bf3<false, false><<<g4, blk, GEMM_SMEM>>>(Oh, Ol, Woh, Wol,
        out, nullptr, nullptr, EDIM, EDIM, EDIM, DIM, 1, 0, 0, 0, 0, 0, 0, 1.0f);
}

// round 17
// speedup vs baseline: 1.0101x; 1.0101x over previous
#include <cuda_runtime.h>
#include <cuda_bf16.h>
#include <math.h>
#include <stdint.h>

#define BATCH 2
#define SEQ   2048
#define DIM   2048
#define NHEAD 8
#define HDIM  256
#define EDIM  (NHEAD * HDIM)   // 2048
#define MROWS (BATCH * SEQ)    // 4096
#define NCB   (SEQ / 128)      // 16 col-blocks per row

// ---------------- scratch (device globals; no cudaMalloc allowed) ----------
__device__ float g_QKVf[(size_t)3 * MROWS * EDIM];          // Q|K|V fp32
__device__ float g_S [(size_t)BATCH * NHEAD * SEQ * SEQ];   // E = exp(s - m_blk)
__device__ float g_sin[SEQ * (HDIM / 2)];
__device__ float g_cos[SEQ * (HDIM / 2)];
__device__ float g_rowm[(size_t)BATCH * NHEAD * NCB * SEQ]; // per-block row max
__device__ float g_rowl[(size_t)BATCH * NHEAD * NCB * SEQ]; // per-block row sumexp

// bf16 hi/lo operand pairs
__device__ __nv_bfloat16 g_xh [(size_t)MROWS * DIM],  g_xl [(size_t)MROWS * DIM];
__device__ __nv_bfloat16 g_Wh [(size_t)3 * EDIM * DIM], g_Wl [(size_t)3 * EDIM * DIM];
__device__ __nv_bfloat16 g_Woh[(size_t)DIM * EDIM],   g_Wol[(size_t)DIM * EDIM];
__device__ __nv_bfloat16 g_Qh [(size_t)MROWS * EDIM], g_Ql [(size_t)MROWS * EDIM];
__device__ __nv_bfloat16 g_Kh [(size_t)MROWS * EDIM], g_Kl [(size_t)MROWS * EDIM];
__device__ __nv_bfloat16 g_Vth[(size_t)MROWS * EDIM], g_Vtl[(size_t)MROWS * EDIM];
__device__ __nv_bfloat16 g_Oh [(size_t)MROWS * EDIM], g_Ol [(size_t)MROWS * EDIM];

// ---------------- helpers ----------------------------------------------------
__device__ __forceinline__ uint32_t s2u(const void* p) {
    return (uint32_t)__cvta_generic_to_shared(p);
}
__device__ __forceinline__ void cpa16(uint32_t s, const void* g) {
    asm volatile("cp.async.cg.shared.global [%0], [%1], 16;" :: "r"(s), "l"(g));
}
#define CP_COMMIT() asm volatile("cp.async.commit_group;" ::: "memory")
#define CP_WAIT1()  asm volatile("cp.async.wait_group 1;" ::: "memory")

// split two floats -> hi bf16x2 + residual lo bf16x2 (x in low 16 bits)
__device__ __forceinline__ void pack_split(float2 f, uint32_t& hi, uint32_t& lo) {
    uint32_t h;
    asm("cvt.rn.bf16x2.f32 %0, %1, %2;" : "=r"(h) : "f"(f.y), "f"(f.x));
    float fyh = __uint_as_float(h & 0xffff0000u);
    float fxh = __uint_as_float(h << 16);
    asm("cvt.rn.bf16x2.f32 %0, %1, %2;" : "=r"(lo) : "f"(f.y - fyh), "f"(f.x - fxh));
    hi = h;
}

__device__ __forceinline__ void mma16816(float* c, const uint32_t* a, const uint32_t* b) {
    asm volatile("mma.sync.aligned.m16n8k16.row.col.f32.bf16.bf16.f32 "
        "{%0,%1,%2,%3},{%4,%5,%6,%7},{%8,%9},{%0,%1,%2,%3};"
        : "+f"(c[0]), "+f"(c[1]), "+f"(c[2]), "+f"(c[3])
        : "r"(a[0]), "r"(a[1]), "r"(a[2]), "r"(a[3]), "r"(b[0]), "r"(b[1]));
}

#define LDSM4(R, addr)                                                          \
    asm volatile("ldmatrix.sync.aligned.m8n8.x4.shared.b16 {%0,%1,%2,%3}, [%4];"\
        : "=r"((R)[0]), "=r"((R)[1]), "=r"((R)[2]), "=r"((R)[3]) : "r"(addr))

// swizzle inside a 128x16 bf16 subtile stored as 16B chunks (row, half-of-k16)
__device__ __forceinline__ uint32_t chunkoff(int row, int half) {
    const int line = row >> 2;
    const int cp = ((row & 3) << 1) | half;
    return (uint32_t)(line * 128 + ((cp ^ (line & 7)) << 4));
}

// ---------------- bf16x3-split tensor-core GEMM (R5-proven mainloop) ---------
// C[m][n] = alpha * sum_k (Ah+Al)[m][k] * (Bh+Bl)[n][k]  (lo*lo dropped)
// STATS: causal scores; epilogue emits per-(row,128-col-block) (max,sumexp)
//        and stores E = exp(s - rowblockmax) instead of raw scores.
#define BM 128
#define BN 128
#define BK 32
#define NS 3
#define T_AHI 0
#define T_ALO 8192
#define T_BHI 16384
#define T_BLO 24576
#define STG   32768
#define GEMM_SMEM (NS * STG)     // 98304

template<bool CAUSAL, bool STATS>
__global__ void __launch_bounds__(256, 2)
gemm_bf3(const __nv_bfloat16* __restrict__ Ahg, const __nv_bfloat16* __restrict__ Alg,
         const __nv_bfloat16* __restrict__ Bhg, const __nv_bfloat16* __restrict__ Blg,
         float* __restrict__ Cg,
         int K, int lda, int ldb, int ldc, int batch_inner,
         long sa_out, long sa_in, long sb_out, long sb_in,
         long sc_out, long sc_in, float alpha)
{
    const int m0 = blockIdx.y * BM;
    const int n0 = blockIdx.x * BN;
    if (CAUSAL && n0 > m0 + BM - 1) return;

    const int z = blockIdx.z, zo = z / batch_inner, zi = z % batch_inner;
    const __nv_bfloat16* Ah = Ahg + zo * sa_out + zi * sa_in + (long)m0 * lda;
    const __nv_bfloat16* Al = Alg + zo * sa_out + zi * sa_in + (long)m0 * lda;
    const __nv_bfloat16* Bh = Bhg + zo * sb_out + zi * sb_in + (long)n0 * ldb;
    const __nv_bfloat16* Bl = Blg + zo * sb_out + zi * sb_in + (long)n0 * ldb;

    extern __shared__ __align__(128) char smem[];
    const uint32_t sbase = s2u(smem);

    const int tid = threadIdx.x, wid = tid >> 5, lane = tid & 31;
    const int wm = wid >> 2, wn = wid & 3;           // warp grid 2 x 4
    const int warp_row = wm * 64, warp_col = wn * 32;

    const int nk = K / BK;

    // ldmatrix geometry (sub-tile 0 offsets; sub 1 adds 4096)
    const int mat = lane >> 3;
    const int lrow = ((mat & 1) << 3) | (lane & 7);
    const int lhalf = mat >> 1;
    uint32_t aoff[4];
#pragma unroll
    for (int i = 0; i < 4; i++)
        aoff[i] = chunkoff(warp_row + i * 16 + lrow, lhalf);
    const int bj = mat >> 1, bhh = mat & 1;
    const uint32_t boff0 = chunkoff(warp_col + bj * 8 + (lane & 7), bhh);
    const uint32_t boff1 = chunkoff(warp_col + 16 + bj * 8 + (lane & 7), bhh);

    auto load_stage = [&](int stage) {
        if (stage >= nk) return;
        const uint32_t s0 = sbase + (stage % NS) * STG;
        const long k0 = (long)stage * BK;
#pragma unroll
        for (int j = 0; j < 2; j++) {
            const int c = tid + j * 256;
            const int row = c >> 2, sub = (c >> 1) & 1, half = c & 1;
            const uint32_t doff = sub * 4096 + chunkoff(row, half);
            const long goff = k0 + sub * 16 + half * 8;
            cpa16(s0 + T_AHI + doff, Ah + (long)row * lda + goff);
            cpa16(s0 + T_ALO + doff, Al + (long)row * lda + goff);
            cpa16(s0 + T_BHI + doff, Bh + (long)row * ldb + goff);
            cpa16(s0 + T_BLO + doff, Bl + (long)row * ldb + goff);
        }
    };

    float acc[4][4][4];
#pragma unroll
    for (int i = 0; i < 4; i++)
#pragma unroll
        for (int j = 0; j < 4; j++)
#pragma unroll
            for (int e = 0; e < 4; e++) acc[i][j][e] = 0.f;

    load_stage(0); CP_COMMIT();
    load_stage(1); CP_COMMIT();

    for (int it = 0; it < nk; it++) {
        CP_WAIT1();
        __syncthreads();
        const uint32_t s0 = sbase + (it % NS) * STG;
#pragma unroll
        for (int sub = 0; sub < 2; sub++) {
            const uint32_t so = s0 + sub * 4096;
            uint32_t bhr[8], blr[8];
            LDSM4(bhr + 0, so + T_BHI + boff0);
            LDSM4(bhr + 4, so + T_BHI + boff1);
            LDSM4(blr + 0, so + T_BLO + boff0);
            LDSM4(blr + 4, so + T_BLO + boff1);
#pragma unroll
            for (int i = 0; i < 4; i++) {
                uint32_t ah[4], al[4];
                LDSM4(ah, so + T_AHI + aoff[i]);
                LDSM4(al, so + T_ALO + aoff[i]);
#pragma unroll
                for (int j = 0; j < 4; j++) {
                    mma16816(acc[i][j], ah, &bhr[j * 2]);   // hi*hi
                    mma16816(acc[i][j], ah, &blr[j * 2]);   // hi*lo
                    mma16816(acc[i][j], al, &bhr[j * 2]);   // lo*hi
                }
            }
        }
        load_stage(it + 2);
        CP_COMMIT();
    }

    // ---------------- epilogue ----------------
    const int r  = lane >> 2;
    const int cq = (lane & 3) * 2;

#pragma unroll
    for (int i = 0; i < 4; i++)
#pragma unroll
        for (int j = 0; j < 4; j++) {
            const int col = n0 + warp_col + j * 8 + cq;
            const int row0 = m0 + warp_row + i * 16 + r;
            const int row1 = row0 + 8;
            acc[i][j][0] *= alpha; acc[i][j][1] *= alpha;
            acc[i][j][2] *= alpha; acc[i][j][3] *= alpha;
            if (CAUSAL) {
                if (col     > row0) acc[i][j][0] = -1e30f;
                if (col + 1 > row0) acc[i][j][1] = -1e30f;
                if (col     > row1) acc[i][j][2] = -1e30f;
                if (col + 1 > row1) acc[i][j][3] = -1e30f;
            }
        }

    if (STATS) {
        __syncthreads();                    // stage smem now dead -> reuse
        float* redm = (float*)smem;         // [4][128]
        float* redl = redm + 512;           // [4][128]
        float* smM  = redm + 1024;          // [128]

        float lm[2][4];
#pragma unroll
        for (int i = 0; i < 4; i++) {
            float a0 = -1e30f, a1 = -1e30f;
#pragma unroll
            for (int j = 0; j < 4; j++) {
                a0 = fmaxf(a0, fmaxf(acc[i][j][0], acc[i][j][1]));
                a1 = fmaxf(a1, fmaxf(acc[i][j][2], acc[i][j][3]));
            }
            lm[0][i] = a0; lm[1][i] = a1;
        }
#pragma unroll
        for (int o = 1; o <= 2; o <<= 1)
#pragma unroll
            for (int i = 0; i < 4; i++) {
                lm[0][i] = fmaxf(lm[0][i], __shfl_xor_sync(0xffffffffu, lm[0][i], o));
                lm[1][i] = fmaxf(lm[1][i], __shfl_xor_sync(0xffffffffu, lm[1][i], o));
            }
        if ((lane & 3) == 0) {
#pragma unroll
            for (int i = 0; i < 4; i++) {
                redm[wn * 128 + warp_row + i * 16 + r]     = lm[0][i];
                redm[wn * 128 + warp_row + i * 16 + r + 8] = lm[1][i];
            }
        }
        __syncthreads();
        if (tid < 128)
            smM[tid] = fmaxf(fmaxf(redm[tid], redm[128 + tid]),
                             fmaxf(redm[256 + tid], redm[384 + tid]));
        __syncthreads();

        // exp pass: overwrite acc with E = exp(acc - M); accumulate sums
        float ls[2][4];
#pragma unroll
        for (int i = 0; i < 4; i++) {
            const float M0 = smM[warp_row + i * 16 + r];
            const float M1 = smM[warp_row + i * 16 + r + 8];
            float s0 = 0.f, s1 = 0.f;
#pragma unroll
            for (int j = 0; j < 4; j++) {
                const float e0 = __expf(acc[i][j][0] - M0);
                const float e1 = __expf(acc[i][j][1] - M0);
                const float e2 = __expf(acc[i][j][2] - M1);
                const float e3 = __expf(acc[i][j][3] - M1);
                acc[i][j][0] = e0; acc[i][j][1] = e1;
                acc[i][j][2] = e2; acc[i][j][3] = e3;
                s0 += e0 + e1;
                s1 += e2 + e3;
            }
            ls[0][i] = s0; ls[1][i] = s1;
        }
#pragma unroll
        for (int o = 1; o <= 2; o <<= 1)
#pragma unroll
            for (int i = 0; i < 4; i++) {
                ls[0][i] += __shfl_xor_sync(0xffffffffu, ls[0][i], o);
                ls[1][i] += __shfl_xor_sync(0xffffffffu, ls[1][i], o);
            }
        if ((lane & 3) == 0) {
#pragma unroll
            for (int i = 0; i < 4; i++) {
                redl[wn * 128 + warp_row + i * 16 + r]     = ls[0][i];
                redl[wn * 128 + warp_row + i * 16 + r + 8] = ls[1][i];
            }
        }
        __syncthreads();
        if (tid < 128) {
            const float L = redl[tid] + redl[128 + tid]
                          + redl[256 + tid] + redl[384 + tid];
            const long si = ((long)z * NCB + (n0 >> 7)) * SEQ + m0 + tid;
            g_rowm[si] = smM[tid];
            g_rowl[si] = L;
        }
    }

    // store C fp32 (STATS: stores E values; else scaled/masked scores)
    float* C = Cg + zo * sc_out + zi * sc_in;
#pragma unroll
    for (int i = 0; i < 4; i++) {
#pragma unroll
        for (int j = 0; j < 4; j++) {
            const int col = n0 + warp_col + j * 8 + cq;
            const int row0 = m0 + warp_row + i * 16 + r;
            const int row1 = row0 + 8;
            *(float2*)(C + (long)row0 * ldc + col) =
                make_float2(acc[i][j][0], acc[i][j][1]);
            *(float2*)(C + (long)row1 * ldc + col) =
                make_float2(acc[i][j][2], acc[i][j][3]);
        }
    }
}

// ---------------- fused softmax + PV v3 (E precomputed; scale-only) ----------
// LPT: heaviest m-blocks (largest m0) launch FIRST via reversed blockIdx.y.
#define FP_PSTG 16384          // per P slot: hi 8KB @0, lo 8KB @8192
#define FP_PLO  8192
#define FP_V0   49152          // 3 P slots
#define FP_VLO  8192
#define FP_VSTG 16384
#define FP_SCALE 98304         // sm_f[NCB][128] = 8KB
#define FP_SMEM (98304 + NCB * 128 * 4)

__global__ void __launch_bounds__(256, 2)
flashpv(const float* __restrict__ Eg,
        const __nv_bfloat16* __restrict__ Vth, const __nv_bfloat16* __restrict__ Vtl,
        __nv_bfloat16* __restrict__ Oh, __nv_bfloat16* __restrict__ Ol)
{
    const int n0 = blockIdx.x * 128;                       // d cols
    const int m0 = (gridDim.y - 1 - blockIdx.y) * 128;     // q rows (LPT order)
    const int bh = blockIdx.z;
    const int b = bh / NHEAD, h = bh % NHEAD;

    const float* Eb = Eg + (long)bh * SEQ * SEQ + (long)m0 * SEQ;
    const __nv_bfloat16* Vh = Vth + ((long)bh * HDIM + n0) * SEQ;
    const __nv_bfloat16* Vl = Vtl + ((long)bh * HDIM + n0) * SEQ;

    extern __shared__ __align__(128) char smem[];
    const uint32_t sbase = s2u(smem);
    float* sm_f = (float*)(smem + FP_SCALE);   // [NCB][128]

    const int tid = threadIdx.x, wid = tid >> 5, lane = tid & 31;
    const int wm = wid >> 2, wn = wid & 3;
    const int warp_row = wm * 64, warp_col = wn * 32;
    const int W = m0 + 128;
    const int nk = W / 32;

    // combine per-block stats -> per-(row, col-block) scale f = exp(m_cb-M)/L
    if (tid < 128) {
        const int nb = (m0 >> 7) + 1;
        float M = -1e30f, L = 0.f;
        for (int cb = 0; cb < nb; cb++) {
            const long si = ((long)bh * NCB + cb) * SEQ + m0 + tid;
            const float m = g_rowm[si];
            const float l = g_rowl[si];
            const float nm = fmaxf(M, m);
            L = L * __expf(M - nm) + l * __expf(m - nm);
            M = nm;
        }
        const float invL = 1.0f / L;
        for (int cb = 0; cb < nb; cb++) {
            const long si = ((long)bh * NCB + cb) * SEQ + m0 + tid;
            sm_f[cb * 128 + tid] = __expf(g_rowm[si] - M) * invL;
        }
    }
    __syncthreads();

    const int mat = lane >> 3;
    const int lrow = ((mat & 1) << 3) | (lane & 7);
    const int lhalf = mat >> 1;
    uint32_t aoff[4];
#pragma unroll
    for (int i = 0; i < 4; i++)
        aoff[i] = chunkoff(warp_row + i * 16 + lrow, lhalf);
    const int bj = mat >> 1, bhh = mat & 1;
    const uint32_t boff0 = chunkoff(warp_col + bj * 8 + (lane & 7), bhh);
    const uint32_t boff1 = chunkoff(warp_col + 16 + bj * 8 + (lane & 7), bhh);

    const int pg_row = tid >> 2, pg_colg = tid & 3;
    const int pg_sub = pg_colg >> 1, pg_half = pg_colg & 1;
    auto produceP = [&](int stage) {
        if (stage >= nk) return;
        const uint32_t ps = sbase + (stage % 3) * FP_PSTG;
        const int k0 = stage * 32;
        const int cb = stage >> 2;
#pragma unroll
        for (int t = 0; t < 2; t++) {
            const int row = pg_row + t * 64;
            const float f = sm_f[cb * 128 + row];
            const float* sp = Eb + (long)row * SEQ + k0 + pg_colg * 8;
            float4 a  = *(const float4*)(sp);
            float4 bb = *(const float4*)(sp + 4);
            uint32_t h0, l0, h1, l1, h2, l2, h3, l3;
            pack_split(make_float2(a.x  * f, a.y  * f), h0, l0);
            pack_split(make_float2(a.z  * f, a.w  * f), h1, l1);
            pack_split(make_float2(bb.x * f, bb.y * f), h2, l2);
            pack_split(make_float2(bb.z * f, bb.w * f), h3, l3);
            const uint32_t off = pg_sub * 4096 + chunkoff(row, pg_half);
            asm volatile("st.shared.v4.b32 [%0], {%1,%2,%3,%4};"
                :: "r"(ps + off), "r"(h0), "r"(h1), "r"(h2), "r"(h3));
            asm volatile("st.shared.v4.b32 [%0], {%1,%2,%3,%4};"
                :: "r"(ps + FP_PLO + off), "r"(l0), "r"(l1), "r"(l2), "r"(l3));
        }
    };

    auto loadV = [&](int stage) {
        if (stage < nk) {
            const uint32_t vs = sbase + FP_V0 + (stage % 3) * FP_VSTG;
            const int k0 = stage * 32;
#pragma unroll
            for (int j = 0; j < 2; j++) {
                const int c = tid + j * 256;
                const int row = c >> 2, sub = (c >> 1) & 1, half = c & 1;
                const uint32_t doff = sub * 4096 + chunkoff(row, half);
                const long goff = k0 + sub * 16 + half * 8;
                cpa16(vs + doff,           Vh + (long)row * SEQ + goff);
                cpa16(vs + FP_VLO + doff,  Vl + (long)row * SEQ + goff);
            }
        }
        CP_COMMIT();
    };

    float acc[4][4][4];
#pragma unroll
    for (int i = 0; i < 4; i++)
#pragma unroll
        for (int j = 0; j < 4; j++)
#pragma unroll
            for (int e = 0; e < 4; e++) acc[i][j][e] = 0.f;

    produceP(0);
    produceP(1);
    loadV(0);
    loadV(1);

    for (int it = 0; it < nk; it++) {
        CP_WAIT1();
        __syncthreads();
        produceP(it + 2);
        const uint32_t ps = sbase + (it % 3) * FP_PSTG;
        const uint32_t vs = sbase + FP_V0 + (it % 3) * FP_VSTG;
#pragma unroll
        for (int sub = 0; sub < 2; sub++) {
            const uint32_t pso = ps + sub * 4096;
            const uint32_t vso = vs + sub * 4096;
            uint32_t bhr[8], blr[8];
            LDSM4(bhr + 0, vso + boff0);
            LDSM4(bhr + 4, vso + boff1);
            LDSM4(blr + 0, vso + FP_VLO + boff0);
            LDSM4(blr + 4, vso + FP_VLO + boff1);
#pragma unroll
            for (int i = 0; i < 4; i++) {
                uint32_t ah[4], al[4];
                LDSM4(ah, pso + aoff[i]);
                LDSM4(al, pso + FP_PLO + aoff[i]);
#pragma unroll
                for (int j = 0; j < 4; j++) {
                    mma16816(acc[i][j], ah, &bhr[j * 2]);
                    mma16816(acc[i][j], ah, &blr[j * 2]);
                    mma16816(acc[i][j], al, &bhr[j * 2]);
                }
            }
        }
        loadV(it + 2);
    }

    const int r  = lane >> 2;
    const int cq = (lane & 3) * 2;
    __nv_bfloat16* Ch = Oh + (long)b * SEQ * EDIM + h * HDIM;
    __nv_bfloat16* Cl = Ol + (long)b * SEQ * EDIM + h * HDIM;
#pragma unroll
    for (int i = 0; i < 4; i++) {
#pragma unroll
        for (int j = 0; j < 4; j++) {
            const int col = n0 + warp_col + j * 8 + cq;
            const int row0 = m0 + warp_row + i * 16 + r;
            const int row1 = row0 + 8;
            uint32_t h0, l0, h1, l1;
            pack_split(make_float2(acc[i][j][0], acc[i][j][1]), h0, l0);
            pack_split(make_float2(acc[i][j][2], acc[i][j][3]), h1, l1);
            *(uint32_t*)(Ch + (long)row0 * EDIM + col) = h0;
            *(uint32_t*)(Cl + (long)row0 * EDIM + col) = l0;
            *(uint32_t*)(Ch + (long)row1 * EDIM + col) = h1;
            *(uint32_t*)(Cl + (long)row1 * EDIM + col) = l1;
        }
    }
}

// ---------------- single-launch preprocessing --------------------------------
// segments: x (8192) | Wq | Wk | Wv (4096 each) | Wo (4096) | rope (1024)
#define SPLIT_BLKS_X  8192
#define SPLIT_BLKS_W  4096
#define SPLIT_BLKS_R  1024
#define SPLIT_TOTAL_BLKS (SPLIT_BLKS_X + 4 * SPLIT_BLKS_W + SPLIT_BLKS_R)

__global__ void __launch_bounds__(256)
split_all(const float* __restrict__ x,  const float* __restrict__ Wq,
          const float* __restrict__ Wk, const float* __restrict__ Wv,
          const float* __restrict__ Wo, const int* __restrict__ pos,
          __nv_bfloat16* __restrict__ xh,  __nv_bfloat16* __restrict__ xl,
          __nv_bfloat16* __restrict__ Wh,  __nv_bfloat16* __restrict__ Wl,
          __nv_bfloat16* __restrict__ Woh, __nv_bfloat16* __restrict__ Wol)
{
    const long WS = (long)EDIM * DIM;
    const int blk = blockIdx.x;

    if (blk >= SPLIT_BLKS_X + 4 * SPLIT_BLKS_W) {   // RoPE tables segment
        const int i = (blk - SPLIT_BLKS_X - 4 * SPLIT_BLKS_W) * 256 + threadIdx.x;
        const int s = i >> 7, fi = i & 127;
        const double inv = exp(-(double)fi * (9.210340371976184 / 128.0));
        const double ang = (double)pos[s] * inv;
        g_sin[i] = (float)sin(ang);
        g_cos[i] = (float)cos(ang);
        return;
    }

    const float* src;
    __nv_bfloat16 *hi, *lo;
    long i;
    if (blk < SPLIT_BLKS_X) {
        src = x; hi = xh; lo = xl;
        i = (long)blk * 256 + threadIdx.x;
    } else if (blk < SPLIT_BLKS_X + SPLIT_BLKS_W) {
        src = Wq; hi = Wh; lo = Wl;
        i = (long)(blk - SPLIT_BLKS_X) * 256 + threadIdx.x;
    } else if (blk < SPLIT_BLKS_X + 2 * SPLIT_BLKS_W) {
        src = Wk; hi = Wh + WS; lo = Wl + WS;
        i = (long)(blk - SPLIT_BLKS_X - SPLIT_BLKS_W) * 256 + threadIdx.x;
    } else if (blk < SPLIT_BLKS_X + 3 * SPLIT_BLKS_W) {
        src = Wv; hi = Wh + 2 * WS; lo = Wl + 2 * WS;
        i = (long)(blk - SPLIT_BLKS_X - 2 * SPLIT_BLKS_W) * 256 + threadIdx.x;
    } else {
        src = Wo; hi = Woh; lo = Wol;
        i = (long)(blk - SPLIT_BLKS_X - 3 * SPLIT_BLKS_W) * 256 + threadIdx.x;
    }
    const float4 v = ((const float4*)src)[i];
    uint32_t h0, l0, h1, l1;
    pack_split(make_float2(v.x, v.y), h0, l0);
    pack_split(make_float2(v.z, v.w), h1, l1);
    ((uint2*)hi)[i] = make_uint2(h0, h1);
    ((uint2*)lo)[i] = make_uint2(l0, l1);
}

// ---------------- warp reductions ------------------------------------------
__device__ __forceinline__ float warp_sum(float v) {
#pragma unroll
    for (int o = 16; o; o >>= 1) v += __shfl_xor_sync(0xffffffffu, v, o);
    return v;
}

// ---------------- fused RMSNorm + RoPE (Q and K in one launch) ---------------
__global__ void __launch_bounds__(HDIM)
rmsnorm_rope_split(const float* __restrict__ Qf, const float* __restrict__ Kf,
                   const float* __restrict__ qw, const float* __restrict__ kw,
                   __nv_bfloat16* __restrict__ Qh, __nv_bfloat16* __restrict__ Ql,
                   __nv_bfloat16* __restrict__ Kh, __nv_bfloat16* __restrict__ Kl)
{
    const int h = blockIdx.x, s = blockIdx.y, t = threadIdx.x;
    const int b = blockIdx.z & 1, sel = blockIdx.z >> 1;
    const float* X = sel ? Kf : Qf;
    const float* w = sel ? kw : qw;
    __nv_bfloat16* Xh = sel ? Kh : Qh;
    __nv_bfloat16* Xl = sel ? Kl : Ql;

    __shared__ float buf[HDIM];
    __shared__ float red[8];

    const int half = HDIM / 2;
    const int fi = (t < half) ? t : t - half;
    const float cs = g_cos[s * half + fi];
    const float sn = g_sin[s * half + fi];

    const long idx = ((long)(b * SEQ + s)) * EDIM + h * HDIM + t;
    const float x = X[idx];
    const int wid = t >> 5, lane = t & 31;

    float ss = warp_sum(x * x);
    if (lane == 0) red[wid] = ss;
    __syncthreads();
    float tot = 0.f;
#pragma unroll
    for (int rr = 0; rr < 8; rr++) tot += red[rr];

    const float xn = x * rsqrtf(tot * (1.0f / HDIM) + 1e-6f) * w[t];
    buf[t] = xn;
    __syncthreads();

    float out;
    if (t < half) out = xn * cs - buf[t + half] * sn;
    else          out = xn * cs + buf[t - half] * sn;

    const __nv_bfloat16 oh = __float2bfloat16(out);
    Xh[idx] = oh;
    Xl[idx] = __float2bfloat16(out - __bfloat162float(oh));
}

// ---------------- V transpose -> bf16 hi/lo  Vt[bh][d][s] --------------------
__global__ void __launch_bounds__(256)
transpose_v_split(const float* __restrict__ V,
                  __nv_bfloat16* __restrict__ Vth, __nv_bfloat16* __restrict__ Vtl)
{
    __shared__ float tile[32][33];
    const int bh = blockIdx.z;
    const int b = bh / NHEAD, h = bh % NHEAD;
    const int s0 = blockIdx.x * 32, d0 = blockIdx.y * 32;
    const int tx = threadIdx.x & 31, ty = threadIdx.x >> 5;

    const float* src = V + (long)b * SEQ * EDIM + h * HDIM;
#pragma unroll
    for (int i = ty; i < 32; i += 8)
        tile[i][tx] = src[(long)(s0 + i) * EDIM + d0 + tx];
    __syncthreads();
    const long dbase = ((long)bh * HDIM + d0) * SEQ + s0;
#pragma unroll
    for (int i = ty; i < 32; i += 8) {
        const float v = tile[tx][i];
        const __nv_bfloat16 vh = __float2bfloat16(v);
        Vth[dbase + (long)i * SEQ + tx] = vh;
        Vtl[dbase + (long)i * SEQ + tx] = __float2bfloat16(v - __bfloat162float(vh));
    }
}

// ---------------- launcher ---------------------------------------------------
extern "C" void kernel_launch(void* const* d_in, const int* in_sizes, int n_in,
                              void* d_out, int out_size)
{
    const float* x   = (const float*)d_in[0];
    const int*   pos = (const int*)  d_in[1];
    const float* Wq  = (const float*)d_in[2];
    const float* Wk  = (const float*)d_in[3];
    const float* Wv  = (const float*)d_in[4];
    const float* Wo  = (const float*)d_in[5];
    const float* qw  = (const float*)d_in[6];
    const float* kw  = (const float*)d_in[7];
    float* out = (float*)d_out;

    float *QKVf, *Sc;
    cudaGetSymbolAddress((void**)&QKVf, g_QKVf);
    cudaGetSymbolAddress((void**)&Sc,   g_S);
    float* Q = QKVf;
    float* K = QKVf + (size_t)MROWS * EDIM;
    float* V = QKVf + (size_t)2 * MROWS * EDIM;

    __nv_bfloat16 *xh, *xl, *Wh, *Wl, *Woh, *Wol;
    __nv_bfloat16 *Qh, *Ql, *Kh, *Kl, *Vth, *Vtl, *Oh, *Ol;
    cudaGetSymbolAddress((void**)&xh,  g_xh);  cudaGetSymbolAddress((void**)&xl,  g_xl);
    cudaGetSymbolAddress((void**)&Wh,  g_Wh);  cudaGetSymbolAddress((void**)&Wl,  g_Wl);
    cudaGetSymbolAddress((void**)&Woh, g_Woh); cudaGetSymbolAddress((void**)&Wol, g_Wol);
    cudaGetSymbolAddress((void**)&Qh,  g_Qh);  cudaGetSymbolAddress((void**)&Ql,  g_Ql);
    cudaGetSymbolAddress((void**)&Kh,  g_Kh);  cudaGetSymbolAddress((void**)&Kl,  g_Kl);
    cudaGetSymbolAddress((void**)&Vth, g_Vth); cudaGetSymbolAddress((void**)&Vtl, g_Vtl);
    cudaGetSymbolAddress((void**)&Oh,  g_Oh);  cudaGetSymbolAddress((void**)&Ol,  g_Ol);

    cudaFuncSetAttribute(gemm_bf3<false, false>,
        cudaFuncAttributeMaxDynamicSharedMemorySize, GEMM_SMEM);
    cudaFuncSetAttribute(gemm_bf3<true, true>,
        cudaFuncAttributeMaxDynamicSharedMemorySize, GEMM_SMEM);
    cudaFuncSetAttribute(flashpv,
        cudaFuncAttributeMaxDynamicSharedMemorySize, FP_SMEM);

    const dim3 blk(256);
    const long SS = (long)SEQ * SEQ;
    const long WSTRIDE = (long)EDIM * DIM;

    // 0) all fp32 -> bf16 hi/lo splits + RoPE tables in ONE launch
    split_all<<<SPLIT_TOTAL_BLKS, 256>>>(x, Wq, Wk, Wv, Wo, pos,
                                         xh, xl, Wh, Wl, Woh, Wol);

    // 1) QKV projections (3 launches; per-launch working set fits L2)
    const dim3 g1(EDIM / BN, MROWS / BM, 1);
    gemm_bf3<false, false><<<g1, blk, GEMM_SMEM>>>(xh, xl, Wh, Wl,
        Q, DIM, DIM, DIM, EDIM, 1, 0, 0, 0, 0, 0, 0, 1.0f);
    gemm_bf3<false, false><<<g1, blk, GEMM_SMEM>>>(xh, xl, Wh + WSTRIDE, Wl + WSTRIDE,
        K, DIM, DIM, DIM, EDIM, 1, 0, 0, 0, 0, 0, 0, 1.0f);
    gemm_bf3<false, false><<<g1, blk, GEMM_SMEM>>>(xh, xl, Wh + 2 * WSTRIDE, Wl + 2 * WSTRIDE,
        V, DIM, DIM, DIM, EDIM, 1, 0, 0, 0, 0, 0, 0, 1.0f);

    // 2) RMSNorm + RoPE on Q and K (one launch, z selects)
    rmsnorm_rope_split<<<dim3(NHEAD, SEQ, BATCH * 2), HDIM>>>(
        Q, K, qw, kw, Qh, Ql, Kh, Kl);

    // 2b) transpose V -> bf16 hi/lo  [bh][d][s]
    transpose_v_split<<<dim3(SEQ / 32, HDIM / 32, BATCH * NHEAD), 256>>>(V, Vth, Vtl);

    // 3) E = exp(scores - rowblockmax), causal, WITH per-block softmax stats
    const dim3 g2(SEQ / BN, SEQ / BM, BATCH * NHEAD);
    gemm_bf3<true, true><<<g2, blk, GEMM_SMEM>>>(Qh, Ql, Kh, Kl,
        Sc, HDIM, EDIM, EDIM, SEQ,
        NHEAD, (long)SEQ * EDIM, HDIM, (long)SEQ * EDIM, HDIM,
        (long)NHEAD * SS, SS, 0.0625f);

    // 4+5) fused scale + PV (P = E * f) -> O bf16 hi/lo  (LPT CTA order)
    flashpv<<<dim3(HDIM / 128, SEQ / 128, BATCH * NHEAD), blk, FP_SMEM>>>(
        Sc, Vth, Vtl, Oh, Ol);

    // 6) out = O Wo^T (fp32 out)
    const dim3 g4(DIM / BN, MROWS / BM, 1);
    gemm_bf3<false, false><<<g4, blk, GEMM_SMEM>>>(Oh, Ol, Woh, Wol,
        out, EDIM, EDIM, EDIM, DIM, 1, 0, 0, 0, 0, 0, 0, 1.0f);
}